// round 3
// baseline (speedup 1.0000x reference)
#include <cuda_runtime.h>
#include <cstdint>

#define BATCH 8
#define NPTS  32768
#define SPTS  512
#define GRP   32
#define BIGF  1e10f
#define R2F   0.04f

#define CLUSTER      8
#define FPS_THREADS  512
#define NWARP        (FPS_THREADS / 32)      // 16
#define NSLOT        (CLUSTER * NWARP)       // 128
#define PTS_BLK      (NPTS / CLUSTER)        // 4096
#define PPT          (PTS_BLK / FPS_THREADS) // 8

#define CPT        32
#define BQ_THREADS 256
#define CAP        128

#define COMB_ELEMS (BATCH * SPTS * (GRP + 1) * 3)  // 405504

__device__ float4 g_xyz4[BATCH * NPTS];

// ---------------------------------------------------------------------------
// helpers
// ---------------------------------------------------------------------------
__device__ __forceinline__ unsigned smem_u32(const void* p) {
    unsigned a;
    asm("{ .reg .u64 t; cvta.to.shared.u64 t, %1; cvt.u32.u64 %0, t; }" : "=r"(a) : "l"(p));
    return a;
}
__device__ __forceinline__ unsigned redux_max_u32(unsigned v) {
    unsigned r; asm("redux.sync.max.u32 %0, %1, 0xffffffff;" : "=r"(r) : "r"(v)); return r;
}
__device__ __forceinline__ unsigned redux_min_u32(unsigned v) {
    unsigned r; asm("redux.sync.min.u32 %0, %1, 0xffffffff;" : "=r"(r) : "r"(v)); return r;
}
__device__ __forceinline__ unsigned mapa_u32(unsigned laddr, unsigned rank) {
    unsigned r; asm("mapa.shared::cluster.u32 %0, %1, %2;" : "=r"(r) : "r"(laddr), "r"(rank));
    return r;
}

#define MBAR_INIT(addr, cnt) \
    asm volatile("mbarrier.init.shared.b64 [%0], %1;" :: "r"(addr), "r"(cnt) : "memory")

#define MBAR_ARRIVE_REMOTE_REL(raddr) \
    asm volatile("mbarrier.arrive.release.cluster.shared::cluster.b64 _, [%0];" \
                 :: "r"(raddr) : "memory")

#define MBAR_WAIT_PARITY_ACQ_CLUSTER(mbar, parity) do {                            \
    unsigned _m = (mbar), _p = (parity), _d;                                       \
    asm volatile("{\n\t.reg .pred p;\n\t"                                          \
        "mbarrier.try_wait.parity.acquire.cluster.shared::cta.b64 p, [%1], %2;\n\t"\
        "selp.b32 %0, 1, 0, p;\n\t}"                                               \
        : "=r"(_d) : "r"(_m), "r"(_p) : "memory");                                 \
    if (!_d) {                                                                     \
        asm volatile("{\n\t.reg .pred P1;\n"                                       \
            "WL_%=:\n\t"                                                           \
            "mbarrier.try_wait.parity.acquire.cluster.shared::cta.b64 P1, [%0], %1;\n\t" \
            "@P1 bra.uni WD_%=;\n\t"                                               \
            "bra.uni WL_%=;\n"                                                     \
            "WD_%=:\n\t}" :: "r"(_m), "r"(_p) : "memory");                         \
    }                                                                              \
} while (0)

#define CLUSTER_SYNC_ASM() do {                                        \
    asm volatile("barrier.cluster.arrive.aligned;" ::: "memory");      \
    asm volatile("barrier.cluster.wait.aligned;" ::: "memory");        \
} while (0)

// ---------------------------------------------------------------------------
// Kernel 0: pack xyz [B,N,3] -> float4
// ---------------------------------------------------------------------------
__global__ void pad_kernel(const float* __restrict__ xyz) {
    int i = blockIdx.x * blockDim.x + threadIdx.x;
    if (i < BATCH * NPTS) {
        g_xyz4[i] = make_float4(xyz[3 * i], xyz[3 * i + 1], xyz[3 * i + 2], 0.f);
    }
}

// ---------------------------------------------------------------------------
// Kernel 1: FPS — flat all-to-all candidate exchange. No __syncthreads in the
// iteration loop: each warp publishes its winner to all 8 CTAs via DSMEM and
// every warp independently waits + reduces the 128 candidates.
// ---------------------------------------------------------------------------
struct __align__(32) Slot {
    unsigned v;        // +0  distance bits (non-negative float)
    unsigned pid;      // +4  global point id
    float    x;        // +8
    float    y;        // +12
    float    z;        // +16
    unsigned pad[3];   // -> 32B
};

__global__ void __cluster_dims__(CLUSTER, 1, 1) __launch_bounds__(FPS_THREADS, 1)
fps_kernel(const int* __restrict__ finit, float* __restrict__ out_cent) {
    const int tid  = threadIdx.x;
    const int lane = tid & 31, wid = tid >> 5;
    unsigned rank;
    asm("mov.u32 %0, %%cluster_ctarank;" : "=r"(rank));
    const int b = blockIdx.x / CLUSTER;
    const float4* __restrict__ xb = g_xyz4 + b * NPTS;

    __shared__ Slot exch[2][NSLOT];            // 8 KB
    __shared__ unsigned long long bars[2];

    if (tid == 0) {
        MBAR_INIT(smem_u32(&bars[0]), NSLOT);  // 16 warps x 8 CTAs arrives
        MBAR_INIT(smem_u32(&bars[1]), NSLOT);
    }
    __syncthreads();
    CLUSTER_SYNC_ASM();   // barrier init visible cluster-wide

    // register-resident points
    float px[PPT], py[PPT], pz[PPT], dd[PPT];
    const int pid0 = rank * PTS_BLK + tid;
#pragma unroll
    for (int i = 0; i < PPT; i++) {
        float4 p = xb[pid0 + i * FPS_THREADS];
        px[i] = p.x; py[i] = p.y; pz[i] = p.z; dd[i] = BIGF;
    }

    const unsigned bar0 = smem_u32(&bars[0]);
    const unsigned bar1 = smem_u32(&bars[1]);
    const unsigned slot0 = smem_u32(&exch[0][rank * NWARP + wid]);
    const unsigned slot1 = smem_u32(&exch[1][rank * NWARP + wid]);

    float4 c0 = xb[finit[b]];
    float cx = c0.x, cy = c0.y, cz = c0.z;

    for (int s = 0; s < SPTS; s++) {
        if (rank == 0 && tid == 0) {
            float* o = out_cent + (size_t)(b * SPTS + s) * 3;
            o[0] = cx; o[1] = cy; o[2] = cz;
        }
        if (s == SPTS - 1) break;

        // ---- per-point min-update + thread argmax (exact mul/add rounding) ----
        float bv = -1.f; unsigned bpid = 0;
#pragma unroll
        for (int i = 0; i < PPT; i++) {
            float dx = px[i] - cx, dy = py[i] - cy, dz = pz[i] - cz;
            float sq = __fadd_rn(__fadd_rn(__fmul_rn(dx, dx), __fmul_rn(dy, dy)),
                                 __fmul_rn(dz, dz));
            float nd = fminf(dd[i], sq);
            dd[i] = nd;
            if (nd > bv) { bv = nd; bpid = (unsigned)(pid0 + i * FPS_THREADS); }
        }

        // ---- warp argmax via REDUX (tie -> smaller pid) ----
        unsigned vb   = __float_as_uint(bv);
        unsigned vmax = redux_max_u32(vb);
        unsigned pidw = redux_min_u32((vb == vmax) ? bpid : 0xffffffffu);

        // owner lane's coords, broadcast to whole warp via shfl
        int osel = (int)((pidw >> 9) & 7);
        float ox = px[0], oy = py[0], oz = pz[0];
#pragma unroll
        for (int j = 1; j < PPT; j++)
            if (osel == j) { ox = px[j]; oy = py[j]; oz = pz[j]; }
        int srcl = (int)(pidw & 31);
        ox = __shfl_sync(0xffffffffu, ox, srcl);
        oy = __shfl_sync(0xffffffffu, oy, srcl);
        oz = __shfl_sync(0xffffffffu, oz, srcl);

        const int bb = s & 1;
        const unsigned ph = (unsigned)((s >> 1) & 1);
        const unsigned lslot = bb ? slot1 : slot0;
        const unsigned lbar  = bb ? bar1  : bar0;

        // ---- lanes 0..7 publish warp winner to rank=lane, then arrive ----
        if (lane < CLUSTER) {
            unsigned rslot = mapa_u32(lslot, (unsigned)lane);
            asm volatile("st.shared::cluster.v4.b32 [%0], {%1,%2,%3,%4};"
                         :: "r"(rslot), "r"(vmax), "r"(pidw),
                            "r"(__float_as_uint(ox)), "r"(__float_as_uint(oy)) : "memory");
            asm volatile("st.shared::cluster.b32 [%0], %1;"
                         :: "r"(rslot + 16u), "r"(__float_as_uint(oz)) : "memory");
            unsigned rbar = mapa_u32(lbar, (unsigned)lane);
            MBAR_ARRIVE_REMOTE_REL(rbar);
        }

        // ---- every warp waits and reduces all 128 candidates itself ----
        MBAR_WAIT_PARITY_ACQ_CLUSTER(lbar, ph);

        unsigned myv[NSLOT / 32], mypid[NSLOT / 32];
#pragma unroll
        for (int j = 0; j < NSLOT / 32; j++) {
            uint2 t = *(const uint2*)&exch[bb][lane + 32 * j];
            myv[j] = t.x; mypid[j] = t.y;
        }
        unsigned cv = myv[0], cp = mypid[0];
#pragma unroll
        for (int j = 1; j < NSLOT / 32; j++)
            if (myv[j] > cv || (myv[j] == cv && mypid[j] < cp)) { cv = myv[j]; cp = mypid[j]; }
        unsigned vm = redux_max_u32(cv);
        unsigned pm = redux_min_u32((cv == vm) ? cp : 0xffffffffu);
        int slot = -1;
#pragma unroll
        for (int j = 0; j < NSLOT / 32; j++)
            if (mypid[j] == pm) slot = lane + 32 * j;
        unsigned mk = __ballot_sync(0xffffffffu, slot >= 0);
        int wl = __ffs(mk) - 1;
        slot = __shfl_sync(0xffffffffu, slot, wl);

        float2 xy = *(const float2*)((const char*)&exch[bb][slot] + 8);
        float nz = exch[bb][slot].z;
        cx = xy.x; cy = xy.y; cz = nz;
    }

    CLUSTER_SYNC_ASM();
}

// ---------------------------------------------------------------------------
// Kernel 2: ball query + group + relative coords (unchanged, proven)
// ---------------------------------------------------------------------------
__global__ void __launch_bounds__(BQ_THREADS, 1)
ball_kernel(const float* __restrict__ cent, float* __restrict__ outc) {
    const int b  = blockIdx.x >> 4;
    const int s0 = (blockIdx.x & 15) * CPT;
    const int tid = threadIdx.x;
    const int lane = tid & 31, wid = tid >> 5;

    __shared__ float4 sc[CPT];
    __shared__ int cnt[CPT];
    __shared__ unsigned long long keys[CPT][CAP];
    __shared__ int sel[CPT][GRP];

    if (tid < CPT) {
        cnt[tid] = 0;
        const float* c = cent + (size_t)(b * SPTS + s0 + tid) * 3;
        sc[tid] = make_float4(c[0], c[1], c[2], 0.f);
    }
    __syncthreads();

    float cxr[CPT], cyr[CPT], czr[CPT];
#pragma unroll
    for (int c = 0; c < CPT; c++) { float4 t = sc[c]; cxr[c] = t.x; cyr[c] = t.y; czr[c] = t.z; }

    const float4* __restrict__ xb = g_xyz4 + b * NPTS;

    for (int pid = tid; pid < NPTS; pid += BQ_THREADS) {
        float4 p = xb[pid];
#pragma unroll
        for (int c = 0; c < CPT; c++) {
            float dx = p.x - cxr[c], dy = p.y - cyr[c], dz = p.z - czr[c];
            float sq = __fadd_rn(__fadd_rn(__fmul_rn(dx, dx), __fmul_rn(dy, dy)),
                                 __fmul_rn(dz, dz));
            if (sq <= R2F) {
                int pos = atomicAdd(&cnt[c], 1);
                if (pos < CAP)
                    keys[c][pos] = ((unsigned long long)__float_as_uint(sq) << 32) | (unsigned)pid;
            }
        }
    }
    __syncthreads();

    for (int k = 0; k < CPT / 8; k++) {
        const int c = wid * (CPT / 8) + k;
        const int m = min(cnt[c], CAP);
        const int K = min(m, GRP);

        unsigned long long kk[CAP / 32];
#pragma unroll
        for (int j = 0; j < CAP / 32; j++) {
            int pos = lane + 32 * j;
            kk[j] = (pos < m) ? keys[c][pos] : 0xFFFFFFFFFFFFFFFFull;
        }
        for (int t = 0; t < K; t++) {
            unsigned long long lm = kk[0];
#pragma unroll
            for (int j = 1; j < CAP / 32; j++) lm = (kk[j] < lm) ? kk[j] : lm;
#pragma unroll
            for (int off = 16; off; off >>= 1) {
                unsigned long long o = __shfl_xor_sync(0xffffffffu, lm, off);
                lm = (o < lm) ? o : lm;
            }
#pragma unroll
            for (int j = 0; j < CAP / 32; j++) if (kk[j] == lm) kk[j] = 0xFFFFFFFFFFFFFFFFull;
            if (lane == 0) sel[c][t] = (int)(unsigned)(lm & 0xFFFFFFFFull);
        }

        int need = GRP - K;
        int base = 0;
        while (need > 0) {
            int id = base + lane;
            bool oor = false;
            if (id < NPTS) {
                float4 p = xb[id];
                float dx = p.x - cxr[c], dy = p.y - cyr[c], dz = p.z - czr[c];
                float sq = __fadd_rn(__fadd_rn(__fmul_rn(dx, dx), __fmul_rn(dy, dy)),
                                     __fmul_rn(dz, dz));
                oor = (sq > R2F);
            }
            unsigned msk = __ballot_sync(0xffffffffu, oor);
            int r = __popc(msk & ((1u << lane) - 1u));
            if (oor && r < need) sel[c][GRP - need + r] = id;
            int take = min(__popc(msk), need);
            need -= take;
            base += 32;
        }
    }
    __syncthreads();

    for (int k = 0; k < CPT / 8; k++) {
        const int c = wid * (CPT / 8) + k;
        const int s = s0 + c;
        float4 cc = sc[c];
        float* ob = outc + (size_t)((b * SPTS + s) * (GRP + 1)) * 3;
        if (lane == 0) { ob[0] = cc.x; ob[1] = cc.y; ob[2] = cc.z; }
        int idx = sel[c][lane];
        float4 p = xb[idx];
        float* og = ob + (size_t)(1 + lane) * 3;
        og[0] = p.x - cc.x; og[1] = p.y - cc.y; og[2] = p.z - cc.z;
    }
}

// ---------------------------------------------------------------------------
extern "C" void kernel_launch(void* const* d_in, const int* in_sizes, int n_in,
                              void* d_out, int out_size) {
    const float* xyz   = (const float*)d_in[0];
    const int*   finit = (const int*)d_in[1];
    float* out  = (float*)d_out;
    float* comb = out;                 // [B,S,33,3]
    float* cent = out + COMB_ELEMS;    // [B,S,3]

    pad_kernel<<<(BATCH * NPTS + 255) / 256, 256>>>(xyz);
    fps_kernel<<<BATCH * CLUSTER, FPS_THREADS>>>(finit, cent);
    ball_kernel<<<BATCH * (SPTS / CPT), BQ_THREADS>>>(cent, comb);
}

// round 4
// speedup vs baseline: 1.1909x; 1.1909x over previous
#include <cuda_runtime.h>
#include <cstdint>

#define BATCH 8
#define NPTS  32768
#define SPTS  512
#define GRP   32
#define BIGF  1e10f
#define R2F   0.04f

#define CLUSTER      8
#define FPS_THREADS  512
#define NWARP        (FPS_THREADS / 32)      // 16
#define PTS_BLK      (NPTS / CLUSTER)        // 4096
#define PPT          (PTS_BLK / FPS_THREADS) // 8
#define TAGM         0x1ffull
#define SENTINEL     0x1ffull                // tag 511 never waited on (s<=510)

#define CPT        32
#define BQ_THREADS 256
#define CAP        128

#define COMB_ELEMS (BATCH * SPTS * (GRP + 1) * 3)  // 405504

__device__ float4 g_xyz4[BATCH * NPTS];

// ---------------------------------------------------------------------------
// helpers
// ---------------------------------------------------------------------------
__device__ __forceinline__ unsigned smem_u32(const void* p) {
    unsigned a;
    asm("{ .reg .u64 t; cvta.to.shared.u64 t, %1; cvt.u32.u64 %0, t; }" : "=r"(a) : "l"(p));
    return a;
}
__device__ __forceinline__ unsigned redux_max_u32(unsigned v) {
    unsigned r; asm("redux.sync.max.u32 %0, %1, 0xffffffff;" : "=r"(r) : "r"(v)); return r;
}
__device__ __forceinline__ unsigned redux_min_u32(unsigned v) {
    unsigned r; asm("redux.sync.min.u32 %0, %1, 0xffffffff;" : "=r"(r) : "r"(v)); return r;
}
__device__ __forceinline__ unsigned mapa_u32(unsigned laddr, unsigned rank) {
    unsigned r; asm("mapa.shared::cluster.u32 %0, %1, %2;" : "=r"(r) : "r"(laddr), "r"(rank));
    return r;
}
// CTA-scope release/acquire (block stage)
__device__ __forceinline__ void st_rel_cta_u64(unsigned a, unsigned long long v) {
    asm volatile("st.release.cta.shared::cta.b64 [%0], %1;" :: "r"(a), "l"(v) : "memory");
}
__device__ __forceinline__ unsigned long long ld_acq_cta_u64(unsigned a) {
    unsigned long long v;
    asm volatile("ld.acquire.cta.shared::cta.b64 %0, [%1];" : "=l"(v) : "r"(a) : "memory");
    return v;
}
// cluster-scope (exchange stage)
__device__ __forceinline__ void st_cluster_u64(unsigned a, unsigned long long v) {
    asm volatile("st.shared::cluster.b64 [%0], %1;" :: "r"(a), "l"(v) : "memory");
}
__device__ __forceinline__ void st_rel_cluster_u64(unsigned a, unsigned long long v) {
    asm volatile("st.release.cluster.shared::cluster.b64 [%0], %1;" :: "r"(a), "l"(v) : "memory");
}
__device__ __forceinline__ unsigned long long ld_acq_cluster_u64(unsigned a) {
    unsigned long long v;
    asm volatile("ld.acquire.cluster.shared::cta.b64 %0, [%1];" : "=l"(v) : "r"(a) : "memory");
    return v;
}

#define CLUSTER_SYNC_ASM() do {                                        \
    asm volatile("barrier.cluster.arrive.aligned;" ::: "memory");      \
    asm volatile("barrier.cluster.wait.aligned;" ::: "memory");        \
} while (0)

// ---------------------------------------------------------------------------
// Kernel 0: pack xyz [B,N,3] -> float4
// ---------------------------------------------------------------------------
__global__ void pad_kernel(const float* __restrict__ xyz) {
    int i = blockIdx.x * blockDim.x + threadIdx.x;
    if (i < BATCH * NPTS) {
        g_xyz4[i] = make_float4(xyz[3 * i], xyz[3 * i + 1], xyz[3 * i + 2], 0.f);
    }
}

// ---------------------------------------------------------------------------
// Kernel 1: FPS — hierarchical candidate exchange with tag-stamped u64 slots
// and spin-waits. No __syncthreads / mbarriers in the iteration loop.
// Slot layout: key = vbits<<32 | pid<<9 | tag ; xy = xbits<<32|ybits ; zw = zbits
// Writer: xy,zw plain; key with release. Reader: key with acquire (tag spin),
// re-acquire winner key, then plain xy/zw.
// ---------------------------------------------------------------------------
struct __align__(8) XSlot { unsigned long long key, xy, zw; };

__global__ void __cluster_dims__(CLUSTER, 1, 1) __launch_bounds__(FPS_THREADS, 1)
fps_kernel(const int* __restrict__ finit, float* __restrict__ out_cent) {
    const int tid  = threadIdx.x;
    const int lane = tid & 31, wid = tid >> 5;
    unsigned rank;
    asm("mov.u32 %0, %%cluster_ctarank;" : "=r"(rank));
    const int b = blockIdx.x / CLUSTER;
    const float4* __restrict__ xb = g_xyz4 + b * NPTS;

    __shared__ XSlot wslot[NWARP];          // block-stage warp winners
    __shared__ XSlot cslot[2][CLUSTER];     // cluster-stage CTA winners (dbl buf)

    if (tid < NWARP) wslot[tid].key = SENTINEL;
    if (tid < 2 * CLUSTER) ((XSlot*)cslot)[tid].key = SENTINEL;
    __syncthreads();
    CLUSTER_SYNC_ASM();   // sentinel init visible before any remote publish

    // register-resident points
    float px[PPT], py[PPT], pz[PPT], dd[PPT];
    const int pid0 = rank * PTS_BLK + tid;
#pragma unroll
    for (int i = 0; i < PPT; i++) {
        float4 p = xb[pid0 + i * FPS_THREADS];
        px[i] = p.x; py[i] = p.y; pz[i] = p.z; dd[i] = BIGF;
    }

    float4 c0 = xb[finit[b]];
    float cx = c0.x, cy = c0.y, cz = c0.z;

    const unsigned my_wslot = smem_u32(&wslot[wid]);
    const unsigned poll_wslot = smem_u32(&wslot[lane & 15]);
    const unsigned poll_cslot0 = smem_u32(&cslot[0][lane & 7]);
    const unsigned poll_cslot1 = smem_u32(&cslot[1][lane & 7]);

    for (int s = 0; s < SPTS; s++) {
        if (rank == 0 && tid == 0) {
            float* o = out_cent + (size_t)(b * SPTS + s) * 3;
            o[0] = cx; o[1] = cy; o[2] = cz;
        }
        if (s == SPTS - 1) break;

        const unsigned tag = (unsigned)(s & 0x1ff);
        const int bb = s & 1;

        // ---- per-point min-update + thread argmax (exact mul/add rounding) ----
        float bv = -1.f; unsigned bpid = 0;
#pragma unroll
        for (int i = 0; i < PPT; i++) {
            float dx = px[i] - cx, dy = py[i] - cy, dz = pz[i] - cz;
            float sq = __fadd_rn(__fadd_rn(__fmul_rn(dx, dx), __fmul_rn(dy, dy)),
                                 __fmul_rn(dz, dz));
            float nd = fminf(dd[i], sq);
            dd[i] = nd;
            if (nd > bv) { bv = nd; bpid = (unsigned)(pid0 + i * FPS_THREADS); }
        }

        // ---- warp argmax (tie -> smaller pid) ----
        unsigned vb   = __float_as_uint(bv);
        unsigned vmax = redux_max_u32(vb);
        unsigned pidw = redux_min_u32((vb == vmax) ? bpid : 0xffffffffu);

        // owner lane's coords -> whole warp
        int osel = (int)((pidw >> 9) & 7);   // local offset / 512
        float ox = px[0], oy = py[0], oz = pz[0];
#pragma unroll
        for (int j = 1; j < PPT; j++)
            if (osel == j) { ox = px[j]; oy = py[j]; oz = pz[j]; }
        int srcl = (int)(pidw & 31);
        ox = __shfl_sync(0xffffffffu, ox, srcl);
        oy = __shfl_sync(0xffffffffu, oy, srcl);
        oz = __shfl_sync(0xffffffffu, oz, srcl);

        // ---- publish warp winner to block slot (lane 0) ----
        if (lane == 0) {
            unsigned long long xy = ((unsigned long long)__float_as_uint(ox) << 32)
                                  | __float_as_uint(oy);
            unsigned long long zw = (unsigned long long)__float_as_uint(oz);
            wslot[wid].xy = xy;
            wslot[wid].zw = zw;
            unsigned long long key = ((unsigned long long)vmax << 32)
                                   | ((unsigned long long)(pidw & 0x7fffu) << 9) | tag;
            st_rel_cta_u64(my_wslot, key);
        }

        // ---- warp0: block reduce + remote publish ----
        if (wid == 0) {
            unsigned long long k;
            bool ok;
            do {
                k = ld_acq_cta_u64(poll_wslot);
                ok = (lane >= 16) || ((unsigned)(k & TAGM) == tag);
            } while (__ballot_sync(0xffffffffu, ok) != 0xffffffffu);

            unsigned v   = (unsigned)(k >> 32);
            unsigned pid = (unsigned)(k >> 9) & 0x7fffu;
            bool valid = (lane < 16);
            unsigned vm = redux_max_u32(valid ? v : 0u);
            unsigned pm = redux_min_u32((valid && v == vm) ? pid : 0xffffffffu);
            unsigned msk = __ballot_sync(0xffffffffu, valid && v == vm && pid == pm);
            int src = __ffs(msk) - 1;

            if (lane < CLUSTER) {
                (void)ld_acq_cta_u64(smem_u32(&wslot[src].key));  // order coords
                unsigned long long xy = wslot[src].xy;
                unsigned long long zw = wslot[src].zw;
                unsigned long long wkey = ((unsigned long long)vm << 32)
                                        | ((unsigned long long)pm << 9) | tag;
                unsigned base = smem_u32(&cslot[bb][rank]);
                unsigned r0 = mapa_u32(base, (unsigned)lane);
                st_cluster_u64(r0 + 8u,  xy);
                st_cluster_u64(r0 + 16u, zw);
                st_rel_cluster_u64(r0, wkey);
            }
        }

        // ---- every warp: wait for 8 CTA candidates, reduce locally ----
        const unsigned pc = bb ? poll_cslot1 : poll_cslot0;
        unsigned long long ck;
        bool cok;
        do {
            ck = ld_acq_cluster_u64(pc);
            cok = (lane >= 8) || ((unsigned)(ck & TAGM) == tag);
        } while (__ballot_sync(0xffffffffu, cok) != 0xffffffffu);

        unsigned cv   = (unsigned)(ck >> 32);
        unsigned cpid = (unsigned)(ck >> 9) & 0x7fffu;
        bool cval = (lane < 8);
        unsigned cvm = redux_max_u32(cval ? cv : 0u);
        unsigned cpm = redux_min_u32((cval && cv == cvm) ? cpid : 0xffffffffu);
        unsigned cmsk = __ballot_sync(0xffffffffu, cval && cv == cvm && cpid == cpm);
        int cs = __ffs(cmsk) - 1;

        (void)ld_acq_cluster_u64(smem_u32(&cslot[bb][cs].key));   // order coords
        unsigned long long xy = cslot[bb][cs].xy;
        unsigned long long zw = cslot[bb][cs].zw;
        cx = __uint_as_float((unsigned)(xy >> 32));
        cy = __uint_as_float((unsigned)xy);
        cz = __uint_as_float((unsigned)zw);
    }

    CLUSTER_SYNC_ASM();   // keep remote stores alive until all CTAs done
}

// ---------------------------------------------------------------------------
// Kernel 2: ball query + group + relative coords (unchanged, proven)
// ---------------------------------------------------------------------------
__global__ void __launch_bounds__(BQ_THREADS, 1)
ball_kernel(const float* __restrict__ cent, float* __restrict__ outc) {
    const int b  = blockIdx.x >> 4;
    const int s0 = (blockIdx.x & 15) * CPT;
    const int tid = threadIdx.x;
    const int lane = tid & 31, wid = tid >> 5;

    __shared__ float4 sc[CPT];
    __shared__ int cnt[CPT];
    __shared__ unsigned long long keys[CPT][CAP];
    __shared__ int sel[CPT][GRP];

    if (tid < CPT) {
        cnt[tid] = 0;
        const float* c = cent + (size_t)(b * SPTS + s0 + tid) * 3;
        sc[tid] = make_float4(c[0], c[1], c[2], 0.f);
    }
    __syncthreads();

    float cxr[CPT], cyr[CPT], czr[CPT];
#pragma unroll
    for (int c = 0; c < CPT; c++) { float4 t = sc[c]; cxr[c] = t.x; cyr[c] = t.y; czr[c] = t.z; }

    const float4* __restrict__ xb = g_xyz4 + b * NPTS;

    for (int pid = tid; pid < NPTS; pid += BQ_THREADS) {
        float4 p = xb[pid];
#pragma unroll
        for (int c = 0; c < CPT; c++) {
            float dx = p.x - cxr[c], dy = p.y - cyr[c], dz = p.z - czr[c];
            float sq = __fadd_rn(__fadd_rn(__fmul_rn(dx, dx), __fmul_rn(dy, dy)),
                                 __fmul_rn(dz, dz));
            if (sq <= R2F) {
                int pos = atomicAdd(&cnt[c], 1);
                if (pos < CAP)
                    keys[c][pos] = ((unsigned long long)__float_as_uint(sq) << 32) | (unsigned)pid;
            }
        }
    }
    __syncthreads();

    for (int k = 0; k < CPT / 8; k++) {
        const int c = wid * (CPT / 8) + k;
        const int m = min(cnt[c], CAP);
        const int K = min(m, GRP);

        unsigned long long kk[CAP / 32];
#pragma unroll
        for (int j = 0; j < CAP / 32; j++) {
            int pos = lane + 32 * j;
            kk[j] = (pos < m) ? keys[c][pos] : 0xFFFFFFFFFFFFFFFFull;
        }
        for (int t = 0; t < K; t++) {
            unsigned long long lm = kk[0];
#pragma unroll
            for (int j = 1; j < CAP / 32; j++) lm = (kk[j] < lm) ? kk[j] : lm;
#pragma unroll
            for (int off = 16; off; off >>= 1) {
                unsigned long long o = __shfl_xor_sync(0xffffffffu, lm, off);
                lm = (o < lm) ? o : lm;
            }
#pragma unroll
            for (int j = 0; j < CAP / 32; j++) if (kk[j] == lm) kk[j] = 0xFFFFFFFFFFFFFFFFull;
            if (lane == 0) sel[c][t] = (int)(unsigned)(lm & 0xFFFFFFFFull);
        }

        int need = GRP - K;
        int base = 0;
        while (need > 0) {
            int id = base + lane;
            bool oor = false;
            if (id < NPTS) {
                float4 p = xb[id];
                float dx = p.x - cxr[c], dy = p.y - cyr[c], dz = p.z - czr[c];
                float sq = __fadd_rn(__fadd_rn(__fmul_rn(dx, dx), __fmul_rn(dy, dy)),
                                     __fmul_rn(dz, dz));
                oor = (sq > R2F);
            }
            unsigned msk = __ballot_sync(0xffffffffu, oor);
            int r = __popc(msk & ((1u << lane) - 1u));
            if (oor && r < need) sel[c][GRP - need + r] = id;
            int take = min(__popc(msk), need);
            need -= take;
            base += 32;
        }
    }
    __syncthreads();

    for (int k = 0; k < CPT / 8; k++) {
        const int c = wid * (CPT / 8) + k;
        const int s = s0 + c;
        float4 cc = sc[c];
        float* ob = outc + (size_t)((b * SPTS + s) * (GRP + 1)) * 3;
        if (lane == 0) { ob[0] = cc.x; ob[1] = cc.y; ob[2] = cc.z; }
        int idx = sel[c][lane];
        float4 p = xb[idx];
        float* og = ob + (size_t)(1 + lane) * 3;
        og[0] = p.x - cc.x; og[1] = p.y - cc.y; og[2] = p.z - cc.z;
    }
}

// ---------------------------------------------------------------------------
extern "C" void kernel_launch(void* const* d_in, const int* in_sizes, int n_in,
                              void* d_out, int out_size) {
    const float* xyz   = (const float*)d_in[0];
    const int*   finit = (const int*)d_in[1];
    float* out  = (float*)d_out;
    float* comb = out;                 // [B,S,33,3]
    float* cent = out + COMB_ELEMS;    // [B,S,3]

    pad_kernel<<<(BATCH * NPTS + 255) / 256, 256>>>(xyz);
    fps_kernel<<<BATCH * CLUSTER, FPS_THREADS>>>(finit, cent);
    ball_kernel<<<BATCH * (SPTS / CPT), BQ_THREADS>>>(cent, comb);
}

// round 5
// speedup vs baseline: 1.3177x; 1.1065x over previous
#include <cuda_runtime.h>
#include <cstdint>

#define BATCH 8
#define NPTS  32768
#define SPTS  512
#define GRP   32
#define BIGF  1e10f
#define R2F   0.04f

#define CLUSTER      8
#define FPS_THREADS  512
#define PTS_BLK      (NPTS / CLUSTER)        // 4096
#define PPT          (PTS_BLK / FPS_THREADS) // 8

#define CPT        32
#define BQ_THREADS 256
#define CAP        128

#define COMB_ELEMS (BATCH * SPTS * (GRP + 1) * 3)  // 405504

__device__ float4 g_xyz4[BATCH * NPTS];

// ---------------------------------------------------------------------------
// helpers
// ---------------------------------------------------------------------------
__device__ __forceinline__ unsigned smem_u32(const void* p) {
    unsigned a;
    asm("{ .reg .u64 t; cvta.to.shared.u64 t, %1; cvt.u32.u64 %0, t; }" : "=r"(a) : "l"(p));
    return a;
}
__device__ __forceinline__ unsigned redux_max_u32(unsigned v) {
    unsigned r; asm("redux.sync.max.u32 %0, %1, 0xffffffff;" : "=r"(r) : "r"(v)); return r;
}
__device__ __forceinline__ unsigned redux_min_u32(unsigned v) {
    unsigned r; asm("redux.sync.min.u32 %0, %1, 0xffffffff;" : "=r"(r) : "r"(v)); return r;
}
__device__ __forceinline__ unsigned mapa_u32(unsigned laddr, unsigned rank) {
    unsigned r; asm("mapa.shared::cluster.u32 %0, %1, %2;" : "=r"(r) : "r"(laddr), "r"(rank));
    return r;
}

// packed f32x2 (Blackwell): IEEE rn per component — bit-identical to scalar rn
#define PACK2(d, lo, hi)  asm("mov.b64 %0, {%1, %2};" : "=l"(d) : "f"(lo), "f"(hi))
#define UNPACK2(lo, hi, s) asm("mov.b64 {%0, %1}, %2;" : "=f"(lo), "=f"(hi) : "l"(s))
#define ADD2(d, a, b) asm("add.rn.f32x2 %0, %1, %2;" : "=l"(d) : "l"(a), "l"(b))
#define MUL2(d, a, b) asm("mul.rn.f32x2 %0, %1, %2;" : "=l"(d) : "l"(a), "l"(b))

__device__ __forceinline__ float negf(float a) {
    return __uint_as_float(__float_as_uint(a) ^ 0x80000000u);
}

#define MBAR_INIT(addr, cnt) \
    asm volatile("mbarrier.init.shared.b64 [%0], %1;" :: "r"(addr), "r"(cnt) : "memory")

#define MBAR_ARRIVE_REMOTE_REL(raddr) \
    asm volatile("mbarrier.arrive.release.cluster.shared::cluster.b64 _, [%0];" \
                 :: "r"(raddr) : "memory")

#define MBAR_WAIT_PARITY_ACQ_CLUSTER(mbar, parity) do {                            \
    unsigned _m = (mbar), _p = (parity), _d;                                       \
    asm volatile("{\n\t.reg .pred p;\n\t"                                          \
        "mbarrier.try_wait.parity.acquire.cluster.shared::cta.b64 p, [%1], %2;\n\t"\
        "selp.b32 %0, 1, 0, p;\n\t}"                                               \
        : "=r"(_d) : "r"(_m), "r"(_p) : "memory");                                 \
    if (!_d) {                                                                     \
        asm volatile("{\n\t.reg .pred P1;\n"                                       \
            "WL_%=:\n\t"                                                           \
            "mbarrier.try_wait.parity.acquire.cluster.shared::cta.b64 P1, [%0], %1;\n\t" \
            "@P1 bra.uni WD_%=;\n\t"                                               \
            "bra.uni WL_%=;\n"                                                     \
            "WD_%=:\n\t}" :: "r"(_m), "r"(_p) : "memory");                         \
    }                                                                              \
} while (0)

#define CLUSTER_SYNC_ASM() do {                                        \
    asm volatile("barrier.cluster.arrive.aligned;" ::: "memory");      \
    asm volatile("barrier.cluster.wait.aligned;" ::: "memory");        \
} while (0)

// ---------------------------------------------------------------------------
// Kernel 0: pack xyz [B,N,3] -> float4
// ---------------------------------------------------------------------------
__global__ void pad_kernel(const float* __restrict__ xyz) {
    int i = blockIdx.x * blockDim.x + threadIdx.x;
    if (i < BATCH * NPTS) {
        g_xyz4[i] = make_float4(xyz[3 * i], xyz[3 * i + 1], xyz[3 * i + 2], 0.f);
    }
}

// ---------------------------------------------------------------------------
// Kernel 1: FPS — R2 skeleton (mbarrier DSMEM exchange, best measured) with
// packed f32x2 distance math (2 points/instr) and a short argmax tail.
// ---------------------------------------------------------------------------
struct __align__(16) Slot { unsigned v; unsigned pid; float x; float y; float z; unsigned pad[3]; };

__global__ void __cluster_dims__(CLUSTER, 1, 1) __launch_bounds__(FPS_THREADS, 1)
fps_kernel(const int* __restrict__ finit, float* __restrict__ out_cent) {
    const int tid  = threadIdx.x;
    const int lane = tid & 31, wid = tid >> 5;
    unsigned rank;
    asm("mov.u32 %0, %%cluster_ctarank;" : "=r"(rank));
    const int b = blockIdx.x / CLUSTER;
    const float4* __restrict__ xb = g_xyz4 + b * NPTS;

    __shared__ Slot exch[2][CLUSTER];
    __shared__ unsigned long long bars[2];
    __shared__ unsigned svb[16], spid[16];
    __shared__ float sx[16], sy[16], sz[16];
    __shared__ float bcx, bcy, bcz;

    if (tid == 0) {
        MBAR_INIT(smem_u32(&bars[0]), CLUSTER);
        MBAR_INIT(smem_u32(&bars[1]), CLUSTER);
    }
    __syncthreads();
    CLUSTER_SYNC_ASM();

    // register-resident points, packed in pairs: slot j holds points (2j, 2j+1)
    unsigned long long pxx[PPT / 2], pyy[PPT / 2], pzz[PPT / 2];
    float dd[PPT];
    const int pid0 = rank * PTS_BLK + tid;
#pragma unroll
    for (int j = 0; j < PPT / 2; j++) {
        float4 a = xb[pid0 + (2 * j) * FPS_THREADS];
        float4 c = xb[pid0 + (2 * j + 1) * FPS_THREADS];
        PACK2(pxx[j], a.x, c.x);
        PACK2(pyy[j], a.y, c.y);
        PACK2(pzz[j], a.z, c.z);
        dd[2 * j] = BIGF; dd[2 * j + 1] = BIGF;
    }

    float4 c0 = xb[finit[b]];
    float cx = c0.x, cy = c0.y, cz = c0.z;

    for (int s = 0; s < SPTS; s++) {
        if (rank == 0 && tid == 0) {
            float* o = out_cent + (size_t)(b * SPTS + s) * 3;
            o[0] = cx; o[1] = cy; o[2] = cz;
        }
        if (s == SPTS - 1) break;

        // ---- packed distance update: (p - c)^2 as p + (-c), exact rn ----
        unsigned long long ncx2, ncy2, ncz2;
        {
            float nx = negf(cx), ny = negf(cy), nz = negf(cz);
            PACK2(ncx2, nx, nx); PACK2(ncy2, ny, ny); PACK2(ncz2, nz, nz);
        }
#pragma unroll
        for (int j = 0; j < PPT / 2; j++) {
            unsigned long long dx2, dy2, dz2, s2;
            ADD2(dx2, pxx[j], ncx2);
            ADD2(dy2, pyy[j], ncy2);
            ADD2(dz2, pzz[j], ncz2);
            MUL2(dx2, dx2, dx2);
            MUL2(dy2, dy2, dy2);
            MUL2(dz2, dz2, dz2);
            ADD2(s2, dx2, dy2);
            ADD2(s2, s2, dz2);
            float lo, hi; UNPACK2(lo, hi, s2);
            dd[2 * j]     = fminf(dd[2 * j], lo);
            dd[2 * j + 1] = fminf(dd[2 * j + 1], hi);
        }

        // ---- thread argmax: fmax tree + first-index select ----
        float m01 = fmaxf(dd[0], dd[1]), m23 = fmaxf(dd[2], dd[3]);
        float m45 = fmaxf(dd[4], dd[5]), m67 = fmaxf(dd[6], dd[7]);
        float bv = fmaxf(fmaxf(m01, m23), fmaxf(m45, m67));
        int bi = PPT - 1;
#pragma unroll
        for (int i = PPT - 2; i >= 0; i--) if (dd[i] == bv) bi = i;
        unsigned bpid = (unsigned)(pid0 + bi * FPS_THREADS);

        // ---- warp argmax via REDUX (tie -> smaller pid) ----
        unsigned vb   = __float_as_uint(bv);
        unsigned vmax = redux_max_u32(vb);
        unsigned pidw = redux_min_u32((vb == vmax) ? bpid : 0xffffffffu);

        // owner lane reconstructs winner coords from its packed registers
        if ((pidw & 511u) == (unsigned)tid) {
            int i = (int)((pidw >> 9) & 7);
            int jj = i >> 1, h = i & 1;
            unsigned long long xx = pxx[0], yy = pyy[0], zz = pzz[0];
#pragma unroll
            for (int q = 1; q < PPT / 2; q++)
                if (jj == q) { xx = pxx[q]; yy = pyy[q]; zz = pzz[q]; }
            float xl, xh, yl, yh, zl, zh;
            UNPACK2(xl, xh, xx); UNPACK2(yl, yh, yy); UNPACK2(zl, zh, zz);
            svb[wid] = vmax; spid[wid] = pidw;
            sx[wid] = h ? xh : xl; sy[wid] = h ? yh : yl; sz[wid] = h ? zh : zl;
        }
        __syncthreads();

        const int bb = s & 1;
        const unsigned ph = (unsigned)((s >> 1) & 1);

        if (wid == 0) {
            // ---- block argmax over 16 warp winners ----
            unsigned v2  = (lane < 16) ? svb[lane] : 0u;
            unsigned vm2 = redux_max_u32(v2);
            unsigned p2  = (lane < 16 && v2 == vm2) ? spid[lane] : 0xffffffffu;
            unsigned pw2 = redux_min_u32(p2);
            unsigned msk = __ballot_sync(0xffffffffu, lane < 16 && spid[lane] == pw2);
            int src = __ffs(msk) - 1;
            float x = sx[src], y = sy[src], z = sz[src];

            // ---- broadcast candidate to all 8 cluster CTAs ----
            if (lane < CLUSTER) {
                unsigned lslot = smem_u32(&exch[bb][rank]);
                unsigned rslot = mapa_u32(lslot, (unsigned)lane);
                asm volatile("st.shared::cluster.v4.b32 [%0], {%1,%2,%3,%4};"
                             :: "r"(rslot), "r"(vm2), "r"(pw2),
                                "r"(__float_as_uint(x)), "r"(__float_as_uint(y)) : "memory");
                asm volatile("st.shared::cluster.b32 [%0], %1;"
                             :: "r"(rslot + 16u), "r"(__float_as_uint(z)) : "memory");
                unsigned rbar = mapa_u32(smem_u32(&bars[bb]), (unsigned)lane);
                MBAR_ARRIVE_REMOTE_REL(rbar);
            }

            // ---- wait for all 8 candidates, cluster argmax ----
            MBAR_WAIT_PARITY_ACQ_CLUSTER(smem_u32(&bars[bb]), ph);

            unsigned v3  = (lane < CLUSTER) ? exch[bb][lane].v   : 0u;
            unsigned p3i = (lane < CLUSTER) ? exch[bb][lane].pid : 0xffffffffu;
            unsigned vm3 = redux_max_u32(v3);
            unsigned pw3 = redux_min_u32((lane < CLUSTER && v3 == vm3) ? p3i : 0xffffffffu);
            unsigned m3  = __ballot_sync(0xffffffffu, lane < CLUSTER && p3i == pw3);
            int src3 = __ffs(m3) - 1;
            if (lane == 0) {
                bcx = exch[bb][src3].x; bcy = exch[bb][src3].y; bcz = exch[bb][src3].z;
            }
        }
        __syncthreads();
        cx = bcx; cy = bcy; cz = bcz;
    }

    CLUSTER_SYNC_ASM();
}

// ---------------------------------------------------------------------------
// Kernel 2: ball query + group — packed f32x2 main loop (2 centroids/instr).
// Selection / padding / output identical to the proven R2 version.
// ---------------------------------------------------------------------------
__global__ void __launch_bounds__(BQ_THREADS, 1)
ball_kernel(const float* __restrict__ cent, float* __restrict__ outc) {
    const int b  = blockIdx.x >> 4;
    const int s0 = (blockIdx.x & 15) * CPT;
    const int tid = threadIdx.x;
    const int lane = tid & 31, wid = tid >> 5;

    __shared__ float4 sc[CPT];
    __shared__ int cnt[CPT];
    __shared__ unsigned long long keys[CPT][CAP];
    __shared__ int sel[CPT][GRP];

    if (tid < CPT) {
        cnt[tid] = 0;
        const float* c = cent + (size_t)(b * SPTS + s0 + tid) * 3;
        sc[tid] = make_float4(c[0], c[1], c[2], 0.f);
    }
    __syncthreads();

    // negated centroid pairs: slot j holds centroids (2j, 2j+1)
    unsigned long long ncx2[CPT / 2], ncy2[CPT / 2], ncz2[CPT / 2];
#pragma unroll
    for (int j = 0; j < CPT / 2; j++) {
        float4 a = sc[2 * j], c = sc[2 * j + 1];
        PACK2(ncx2[j], negf(a.x), negf(c.x));
        PACK2(ncy2[j], negf(a.y), negf(c.y));
        PACK2(ncz2[j], negf(a.z), negf(c.z));
    }

    const float4* __restrict__ xb = g_xyz4 + b * NPTS;

    for (int pid = tid; pid < NPTS; pid += BQ_THREADS) {
        float4 p = xb[pid];
        unsigned long long px2, py2, pz2;
        PACK2(px2, p.x, p.x); PACK2(py2, p.y, p.y); PACK2(pz2, p.z, p.z);
#pragma unroll
        for (int j = 0; j < CPT / 2; j++) {
            unsigned long long dx2, dy2, dz2, s2;
            ADD2(dx2, px2, ncx2[j]);
            ADD2(dy2, py2, ncy2[j]);
            ADD2(dz2, pz2, ncz2[j]);
            MUL2(dx2, dx2, dx2);
            MUL2(dy2, dy2, dy2);
            MUL2(dz2, dz2, dz2);
            ADD2(s2, dx2, dy2);
            ADD2(s2, s2, dz2);
            float lo, hi; UNPACK2(lo, hi, s2);
            if (lo <= R2F) {
                int pos = atomicAdd(&cnt[2 * j], 1);
                if (pos < CAP)
                    keys[2 * j][pos] = ((unsigned long long)__float_as_uint(lo) << 32) | (unsigned)pid;
            }
            if (hi <= R2F) {
                int pos = atomicAdd(&cnt[2 * j + 1], 1);
                if (pos < CAP)
                    keys[2 * j + 1][pos] = ((unsigned long long)__float_as_uint(hi) << 32) | (unsigned)pid;
            }
        }
    }
    __syncthreads();

    for (int k = 0; k < CPT / 8; k++) {
        const int c = wid * (CPT / 8) + k;
        const int m = min(cnt[c], CAP);
        const int K = min(m, GRP);

        unsigned long long kk[CAP / 32];
#pragma unroll
        for (int j = 0; j < CAP / 32; j++) {
            int pos = lane + 32 * j;
            kk[j] = (pos < m) ? keys[c][pos] : 0xFFFFFFFFFFFFFFFFull;
        }
        for (int t = 0; t < K; t++) {
            unsigned long long lm = kk[0];
#pragma unroll
            for (int j = 1; j < CAP / 32; j++) lm = (kk[j] < lm) ? kk[j] : lm;
#pragma unroll
            for (int off = 16; off; off >>= 1) {
                unsigned long long o = __shfl_xor_sync(0xffffffffu, lm, off);
                lm = (o < lm) ? o : lm;
            }
#pragma unroll
            for (int j = 0; j < CAP / 32; j++) if (kk[j] == lm) kk[j] = 0xFFFFFFFFFFFFFFFFull;
            if (lane == 0) sel[c][t] = (int)(unsigned)(lm & 0xFFFFFFFFull);
        }

        // padding: smallest indices with dist > r^2 (scalar exact, rare path)
        float ccx, ccy, ccz;
        { float4 t4 = sc[c]; ccx = t4.x; ccy = t4.y; ccz = t4.z; }
        int need = GRP - K;
        int base = 0;
        while (need > 0) {
            int id = base + lane;
            bool oor = false;
            if (id < NPTS) {
                float4 p = xb[id];
                float dx = p.x - ccx, dy = p.y - ccy, dz = p.z - ccz;
                float sq = __fadd_rn(__fadd_rn(__fmul_rn(dx, dx), __fmul_rn(dy, dy)),
                                     __fmul_rn(dz, dz));
                oor = (sq > R2F);
            }
            unsigned msk = __ballot_sync(0xffffffffu, oor);
            int r = __popc(msk & ((1u << lane) - 1u));
            if (oor && r < need) sel[c][GRP - need + r] = id;
            int take = min(__popc(msk), need);
            need -= take;
            base += 32;
        }
    }
    __syncthreads();

    for (int k = 0; k < CPT / 8; k++) {
        const int c = wid * (CPT / 8) + k;
        const int s = s0 + c;
        float4 cc = sc[c];
        float* ob = outc + (size_t)((b * SPTS + s) * (GRP + 1)) * 3;
        if (lane == 0) { ob[0] = cc.x; ob[1] = cc.y; ob[2] = cc.z; }
        int idx = sel[c][lane];
        float4 p = xb[idx];
        float* og = ob + (size_t)(1 + lane) * 3;
        og[0] = p.x - cc.x; og[1] = p.y - cc.y; og[2] = p.z - cc.z;
    }
}

// ---------------------------------------------------------------------------
extern "C" void kernel_launch(void* const* d_in, const int* in_sizes, int n_in,
                              void* d_out, int out_size) {
    const float* xyz   = (const float*)d_in[0];
    const int*   finit = (const int*)d_in[1];
    float* out  = (float*)d_out;
    float* comb = out;                 // [B,S,33,3]
    float* cent = out + COMB_ELEMS;    // [B,S,3]

    pad_kernel<<<(BATCH * NPTS + 255) / 256, 256>>>(xyz);
    fps_kernel<<<BATCH * CLUSTER, FPS_THREADS>>>(finit, cent);
    ball_kernel<<<BATCH * (SPTS / CPT), BQ_THREADS>>>(cent, comb);
}

// round 6
// speedup vs baseline: 1.3783x; 1.0460x over previous
#include <cuda_runtime.h>
#include <cstdint>

#define BATCH 8
#define NPTS  32768
#define SPTS  512
#define GRP   32
#define BIGF  1e10f
#define R2F   0.04f

#define CLUSTER      8
#define FPS_THREADS  128
#define FPS_NWARP    (FPS_THREADS / 32)      // 4
#define PTS_BLK      (NPTS / CLUSTER)        // 4096
#define PPT          (PTS_BLK / FPS_THREADS) // 32
#define NP2          (PPT / 2)               // 16 packed slots

#define CPT        32
#define BQ_THREADS 256
#define CAP        128

#define COMB_ELEMS (BATCH * SPTS * (GRP + 1) * 3)  // 405504

__device__ float4 g_xyz4[BATCH * NPTS];

// ---------------------------------------------------------------------------
// helpers
// ---------------------------------------------------------------------------
__device__ __forceinline__ unsigned smem_u32(const void* p) {
    unsigned a;
    asm("{ .reg .u64 t; cvta.to.shared.u64 t, %1; cvt.u32.u64 %0, t; }" : "=r"(a) : "l"(p));
    return a;
}
__device__ __forceinline__ unsigned redux_max_u32(unsigned v) {
    unsigned r; asm("redux.sync.max.u32 %0, %1, 0xffffffff;" : "=r"(r) : "r"(v)); return r;
}
__device__ __forceinline__ unsigned redux_min_u32(unsigned v) {
    unsigned r; asm("redux.sync.min.u32 %0, %1, 0xffffffff;" : "=r"(r) : "r"(v)); return r;
}
__device__ __forceinline__ unsigned mapa_u32(unsigned laddr, unsigned rank) {
    unsigned r; asm("mapa.shared::cluster.u32 %0, %1, %2;" : "=r"(r) : "r"(laddr), "r"(rank));
    return r;
}

// packed f32x2 (Blackwell): IEEE rn per component — bit-identical to scalar rn
#define PACK2(d, lo, hi)  asm("mov.b64 %0, {%1, %2};" : "=l"(d) : "f"(lo), "f"(hi))
#define UNPACK2(lo, hi, s) asm("mov.b64 {%0, %1}, %2;" : "=f"(lo), "=f"(hi) : "l"(s))
#define ADD2(d, a, b) asm("add.rn.f32x2 %0, %1, %2;" : "=l"(d) : "l"(a), "l"(b))
#define MUL2(d, a, b) asm("mul.rn.f32x2 %0, %1, %2;" : "=l"(d) : "l"(a), "l"(b))

__device__ __forceinline__ float negf(float a) {
    return __uint_as_float(__float_as_uint(a) ^ 0x80000000u);
}

#define MBAR_INIT(addr, cnt) \
    asm volatile("mbarrier.init.shared.b64 [%0], %1;" :: "r"(addr), "r"(cnt) : "memory")

#define MBAR_ARRIVE_REMOTE_REL(raddr) \
    asm volatile("mbarrier.arrive.release.cluster.shared::cluster.b64 _, [%0];" \
                 :: "r"(raddr) : "memory")

#define MBAR_WAIT_PARITY_ACQ_CLUSTER(mbar, parity) do {                            \
    unsigned _m = (mbar), _p = (parity), _d;                                       \
    asm volatile("{\n\t.reg .pred p;\n\t"                                          \
        "mbarrier.try_wait.parity.acquire.cluster.shared::cta.b64 p, [%1], %2;\n\t"\
        "selp.b32 %0, 1, 0, p;\n\t}"                                               \
        : "=r"(_d) : "r"(_m), "r"(_p) : "memory");                                 \
    if (!_d) {                                                                     \
        asm volatile("{\n\t.reg .pred P1;\n"                                       \
            "WL_%=:\n\t"                                                           \
            "mbarrier.try_wait.parity.acquire.cluster.shared::cta.b64 P1, [%0], %1;\n\t" \
            "@P1 bra.uni WD_%=;\n\t"                                               \
            "bra.uni WL_%=;\n"                                                     \
            "WD_%=:\n\t}" :: "r"(_m), "r"(_p) : "memory");                         \
    }                                                                              \
} while (0)

#define CLUSTER_SYNC_ASM() do {                                        \
    asm volatile("barrier.cluster.arrive.aligned;" ::: "memory");      \
    asm volatile("barrier.cluster.wait.aligned;" ::: "memory");        \
} while (0)

// ---------------------------------------------------------------------------
// Kernel 0: pack xyz [B,N,3] -> float4
// ---------------------------------------------------------------------------
__global__ void pad_kernel(const float* __restrict__ xyz) {
    int i = blockIdx.x * blockDim.x + threadIdx.x;
    if (i < BATCH * NPTS) {
        g_xyz4[i] = make_float4(xyz[3 * i], xyz[3 * i + 1], xyz[3 * i + 2], 0.f);
    }
}

// ---------------------------------------------------------------------------
// Kernel 1: FPS — 8-CTA cluster per batch, 128 threads/CTA (32 pts/thread in
// packed f32x2). Candidates are bare u64 (dist<<32|pid); winner coords are
// re-loaded from global. One __syncthreads per iteration; every warp waits on
// the mbarrier and reduces the 8 cluster slots itself.
// ---------------------------------------------------------------------------
__global__ void __cluster_dims__(CLUSTER, 1, 1) __launch_bounds__(FPS_THREADS, 1)
fps_kernel(const int* __restrict__ finit, float* __restrict__ out_cent) {
    const int tid  = threadIdx.x;
    const int lane = tid & 31, wid = tid >> 5;
    unsigned rank;
    asm("mov.u32 %0, %%cluster_ctarank;" : "=r"(rank));
    const int b = blockIdx.x / CLUSTER;
    const float4* __restrict__ xb = g_xyz4 + b * NPTS;

    __shared__ unsigned long long wslot[FPS_NWARP];    // block-stage warp winners
    __shared__ unsigned long long cslot[2][CLUSTER];   // cluster-stage CTA winners
    __shared__ unsigned long long bars[2];

    if (tid == 0) {
        MBAR_INIT(smem_u32(&bars[0]), CLUSTER);
        MBAR_INIT(smem_u32(&bars[1]), CLUSTER);
    }
    __syncthreads();
    CLUSTER_SYNC_ASM();   // barrier init visible cluster-wide

    // register-resident points, packed pairs: slot j = points (2j, 2j+1),
    // point i lives at pid0 + i*FPS_THREADS
    unsigned long long pxx[NP2], pyy[NP2], pzz[NP2];
    float dd[PPT];
    const int pid0 = rank * PTS_BLK + tid;
#pragma unroll
    for (int j = 0; j < NP2; j++) {
        float4 a = xb[pid0 + (2 * j) * FPS_THREADS];
        float4 c = xb[pid0 + (2 * j + 1) * FPS_THREADS];
        PACK2(pxx[j], a.x, c.x);
        PACK2(pyy[j], a.y, c.y);
        PACK2(pzz[j], a.z, c.z);
        dd[2 * j] = BIGF; dd[2 * j + 1] = BIGF;
    }

    float4 c0 = xb[finit[b]];
    float cx = c0.x, cy = c0.y, cz = c0.z;

    for (int s = 0; s < SPTS; s++) {
        if (rank == 0 && tid == 0) {
            float* o = out_cent + (size_t)(b * SPTS + s) * 3;
            o[0] = cx; o[1] = cy; o[2] = cz;
        }
        if (s == SPTS - 1) break;

        // ---- packed distance update: (p - c)^2 as p + (-c), exact rn ----
        unsigned long long ncx2, ncy2, ncz2;
        {
            float nx = negf(cx), ny = negf(cy), nz = negf(cz);
            PACK2(ncx2, nx, nx); PACK2(ncy2, ny, ny); PACK2(ncz2, nz, nz);
        }
#pragma unroll
        for (int j = 0; j < NP2; j++) {
            unsigned long long dx2, dy2, dz2, s2;
            ADD2(dx2, pxx[j], ncx2);
            ADD2(dy2, pyy[j], ncy2);
            ADD2(dz2, pzz[j], ncz2);
            MUL2(dx2, dx2, dx2);
            MUL2(dy2, dy2, dy2);
            MUL2(dz2, dz2, dz2);
            ADD2(s2, dx2, dy2);
            ADD2(s2, s2, dz2);
            float lo, hi; UNPACK2(lo, hi, s2);
            dd[2 * j]     = fminf(dd[2 * j], lo);
            dd[2 * j + 1] = fminf(dd[2 * j + 1], hi);
        }

        // ---- thread argmax: fmax tree + equality bitmask (lowest i wins) ----
        float t16[16];
#pragma unroll
        for (int i = 0; i < 16; i++) t16[i] = fmaxf(dd[i], dd[i + 16]);
        float t8[8];
#pragma unroll
        for (int i = 0; i < 8; i++) t8[i] = fmaxf(t16[i], t16[i + 8]);
        float t4a = fmaxf(t8[0], t8[4]), t4b = fmaxf(t8[1], t8[5]);
        float t4c = fmaxf(t8[2], t8[6]), t4d = fmaxf(t8[3], t8[7]);
        float bv = fmaxf(fmaxf(t4a, t4b), fmaxf(t4c, t4d));
        unsigned m = 0;
#pragma unroll
        for (int i = 0; i < PPT; i++) m |= (dd[i] == bv) ? (1u << i) : 0u;
        int bi = __ffs(m) - 1;
        unsigned bpid = (unsigned)(pid0 + bi * FPS_THREADS);

        // ---- warp argmax via REDUX (tie -> smaller pid) ----
        unsigned vb   = __float_as_uint(bv);
        unsigned vmax = redux_max_u32(vb);
        unsigned pidw = redux_min_u32((vb == vmax) ? bpid : 0xffffffffu);

        if (lane == 0)
            wslot[wid] = ((unsigned long long)vmax << 32) | pidw;
        __syncthreads();

        const int bb = s & 1;
        const unsigned ph = (unsigned)((s >> 1) & 1);

        // ---- warp0: block reduce over 4 warp slots, publish to 8 CTAs ----
        if (wid == 0) {
            unsigned long long k = (lane < FPS_NWARP) ? wslot[lane] : 0ull;
            unsigned v   = (unsigned)(k >> 32);
            unsigned pid = (unsigned)k;
            unsigned vm2 = redux_max_u32((lane < FPS_NWARP) ? v : 0u);
            unsigned pm2 = redux_min_u32((lane < FPS_NWARP && v == vm2) ? pid : 0xffffffffu);
            if (lane < CLUSTER) {
                unsigned long long key = ((unsigned long long)vm2 << 32) | pm2;
                unsigned lslot = smem_u32(&cslot[bb][rank]);
                unsigned rslot = mapa_u32(lslot, (unsigned)lane);
                asm volatile("st.shared::cluster.b64 [%0], %1;"
                             :: "r"(rslot), "l"(key) : "memory");
                unsigned rbar = mapa_u32(smem_u32(&bars[bb]), (unsigned)lane);
                MBAR_ARRIVE_REMOTE_REL(rbar);
            }
        }

        // ---- every warp: wait for 8 CTA candidates, reduce locally ----
        MBAR_WAIT_PARITY_ACQ_CLUSTER(smem_u32(&bars[bb]), ph);

        unsigned long long ck = (lane < CLUSTER) ? cslot[bb][lane] : 0ull;
        unsigned cv  = (unsigned)(ck >> 32);
        unsigned cp  = (unsigned)ck;
        unsigned cvm = redux_max_u32((lane < CLUSTER) ? cv : 0u);
        unsigned cpm = redux_min_u32((lane < CLUSTER && cv == cvm) ? cp : 0xffffffffu);

        // winner coords from global (uniform address -> broadcast load)
        float4 w = xb[cpm];
        cx = w.x; cy = w.y; cz = w.z;
    }

    CLUSTER_SYNC_ASM();
}

// ---------------------------------------------------------------------------
// Kernel 2: ball query + group — packed f32x2 main loop (proven R5 version).
// ---------------------------------------------------------------------------
__global__ void __launch_bounds__(BQ_THREADS, 1)
ball_kernel(const float* __restrict__ cent, float* __restrict__ outc) {
    const int b  = blockIdx.x >> 4;
    const int s0 = (blockIdx.x & 15) * CPT;
    const int tid = threadIdx.x;
    const int lane = tid & 31, wid = tid >> 5;

    __shared__ float4 sc[CPT];
    __shared__ int cnt[CPT];
    __shared__ unsigned long long keys[CPT][CAP];
    __shared__ int sel[CPT][GRP];

    if (tid < CPT) {
        cnt[tid] = 0;
        const float* c = cent + (size_t)(b * SPTS + s0 + tid) * 3;
        sc[tid] = make_float4(c[0], c[1], c[2], 0.f);
    }
    __syncthreads();

    unsigned long long ncx2[CPT / 2], ncy2[CPT / 2], ncz2[CPT / 2];
#pragma unroll
    for (int j = 0; j < CPT / 2; j++) {
        float4 a = sc[2 * j], c = sc[2 * j + 1];
        PACK2(ncx2[j], negf(a.x), negf(c.x));
        PACK2(ncy2[j], negf(a.y), negf(c.y));
        PACK2(ncz2[j], negf(a.z), negf(c.z));
    }

    const float4* __restrict__ xb = g_xyz4 + b * NPTS;

    for (int pid = tid; pid < NPTS; pid += BQ_THREADS) {
        float4 p = xb[pid];
        unsigned long long px2, py2, pz2;
        PACK2(px2, p.x, p.x); PACK2(py2, p.y, p.y); PACK2(pz2, p.z, p.z);
#pragma unroll
        for (int j = 0; j < CPT / 2; j++) {
            unsigned long long dx2, dy2, dz2, s2;
            ADD2(dx2, px2, ncx2[j]);
            ADD2(dy2, py2, ncy2[j]);
            ADD2(dz2, pz2, ncz2[j]);
            MUL2(dx2, dx2, dx2);
            MUL2(dy2, dy2, dy2);
            MUL2(dz2, dz2, dz2);
            ADD2(s2, dx2, dy2);
            ADD2(s2, s2, dz2);
            float lo, hi; UNPACK2(lo, hi, s2);
            if (lo <= R2F) {
                int pos = atomicAdd(&cnt[2 * j], 1);
                if (pos < CAP)
                    keys[2 * j][pos] = ((unsigned long long)__float_as_uint(lo) << 32) | (unsigned)pid;
            }
            if (hi <= R2F) {
                int pos = atomicAdd(&cnt[2 * j + 1], 1);
                if (pos < CAP)
                    keys[2 * j + 1][pos] = ((unsigned long long)__float_as_uint(hi) << 32) | (unsigned)pid;
            }
        }
    }
    __syncthreads();

    for (int k = 0; k < CPT / 8; k++) {
        const int c = wid * (CPT / 8) + k;
        const int m = min(cnt[c], CAP);
        const int K = min(m, GRP);

        unsigned long long kk[CAP / 32];
#pragma unroll
        for (int j = 0; j < CAP / 32; j++) {
            int pos = lane + 32 * j;
            kk[j] = (pos < m) ? keys[c][pos] : 0xFFFFFFFFFFFFFFFFull;
        }
        for (int t = 0; t < K; t++) {
            unsigned long long lm = kk[0];
#pragma unroll
            for (int j = 1; j < CAP / 32; j++) lm = (kk[j] < lm) ? kk[j] : lm;
#pragma unroll
            for (int off = 16; off; off >>= 1) {
                unsigned long long o = __shfl_xor_sync(0xffffffffu, lm, off);
                lm = (o < lm) ? o : lm;
            }
#pragma unroll
            for (int j = 0; j < CAP / 32; j++) if (kk[j] == lm) kk[j] = 0xFFFFFFFFFFFFFFFFull;
            if (lane == 0) sel[c][t] = (int)(unsigned)(lm & 0xFFFFFFFFull);
        }

        float ccx, ccy, ccz;
        { float4 t4 = sc[c]; ccx = t4.x; ccy = t4.y; ccz = t4.z; }
        int need = GRP - K;
        int base = 0;
        while (need > 0) {
            int id = base + lane;
            bool oor = false;
            if (id < NPTS) {
                float4 p = xb[id];
                float dx = p.x - ccx, dy = p.y - ccy, dz = p.z - ccz;
                float sq = __fadd_rn(__fadd_rn(__fmul_rn(dx, dx), __fmul_rn(dy, dy)),
                                     __fmul_rn(dz, dz));
                oor = (sq > R2F);
            }
            unsigned msk = __ballot_sync(0xffffffffu, oor);
            int r = __popc(msk & ((1u << lane) - 1u));
            if (oor && r < need) sel[c][GRP - need + r] = id;
            int take = min(__popc(msk), need);
            need -= take;
            base += 32;
        }
    }
    __syncthreads();

    for (int k = 0; k < CPT / 8; k++) {
        const int c = wid * (CPT / 8) + k;
        const int s = s0 + c;
        float4 cc = sc[c];
        float* ob = outc + (size_t)((b * SPTS + s) * (GRP + 1)) * 3;
        if (lane == 0) { ob[0] = cc.x; ob[1] = cc.y; ob[2] = cc.z; }
        int idx = sel[c][lane];
        float4 p = xb[idx];
        float* og = ob + (size_t)(1 + lane) * 3;
        og[0] = p.x - cc.x; og[1] = p.y - cc.y; og[2] = p.z - cc.z;
    }
}

// ---------------------------------------------------------------------------
extern "C" void kernel_launch(void* const* d_in, const int* in_sizes, int n_in,
                              void* d_out, int out_size) {
    const float* xyz   = (const float*)d_in[0];
    const int*   finit = (const int*)d_in[1];
    float* out  = (float*)d_out;
    float* comb = out;                 // [B,S,33,3]
    float* cent = out + COMB_ELEMS;    // [B,S,3]

    pad_kernel<<<(BATCH * NPTS + 255) / 256, 256>>>(xyz);
    fps_kernel<<<BATCH * CLUSTER, FPS_THREADS>>>(finit, cent);
    ball_kernel<<<BATCH * (SPTS / CPT), BQ_THREADS>>>(cent, comb);
}